// round 4
// baseline (speedup 1.0000x reference)
#include <cuda_runtime.h>
#include <cstdint>

#define NROWS 16384   // C*N
#define NCOLS 4096    // N
#define INF_  512
#define OUTF  128

// ---------------- device globals (no allocations allowed) ----------------
__device__ double g_sum;
__device__ float  g_mean;
__device__ int    g_colmax[NCOLS];     // float bits as int (attention >= 0)
__device__ float  g_colsum[NCOLS];
__device__ float  g_colscale[NCOLS];   // 2.5 / colsum   (2.5 = 1/(1-0.6))
__device__ float  g_hT[OUTF * NCOLS];  // h transposed [f][n], tf32-rounded
__device__ int    g_mask_mode;         // 0=int32, 1=uint8(bool), 2=float32

// ---------------- helpers ----------------
__device__ __forceinline__ float to_tf32(float x) {
    unsigned u;
    asm("cvt.rna.tf32.f32 %0, %1;" : "=r"(u) : "f"(x));
    return __uint_as_float(u);
}

__device__ __forceinline__ void mma_tf32(float* c, const unsigned* a, unsigned b0, unsigned b1) {
    asm volatile(
        "mma.sync.aligned.m16n8k8.row.col.f32.tf32.tf32.f32 "
        "{%0,%1,%2,%3}, {%4,%5,%6,%7}, {%8,%9}, {%0,%1,%2,%3};\n"
        : "+f"(c[0]), "+f"(c[1]), "+f"(c[2]), "+f"(c[3])
        : "r"(a[0]), "r"(a[1]), "r"(a[2]), "r"(a[3]), "r"(b0), "r"(b1));
}

// ---------------- kernel 0: init ----------------
__global__ void k_init() {
    int id = blockIdx.x * blockDim.x + threadIdx.x;
    if (id < NCOLS) {
        g_colmax[id] = (int)0xFF800000;  // -inf bits
        g_colsum[id] = 0.f;
    }
    if (id == 0) g_sum = 0.0;
}

// ---------------- kernel 0b: detect mask dtype ----------------
__global__ void k_detect(const unsigned char* __restrict__ m) {
    __shared__ int f1, f23;
    if (threadIdx.x == 0) { f1 = 0; f23 = 0; }
    __syncthreads();
    for (int i = threadIdx.x; i < 65536; i += blockDim.x) {
        if (m[i]) {
            int r = i & 3;
            if (r == 1) f1 = 1;
            else if (r >= 2) f23 = 1;
        }
    }
    __syncthreads();
    if (threadIdx.x == 0) g_mask_mode = f1 ? 1 : (f23 ? 2 : 0);
}

// ---------------- kernel 1: global sum (double-accurate) + per-column max ----------------
__global__ __launch_bounds__(1024) void k_stats1(const float* __restrict__ att) {
    const int t = threadIdx.x;
    const int row0 = blockIdx.x * 64;
    const float4* p = (const float4*)att;
    float m0 = -1e30f, m1 = -1e30f, m2 = -1e30f, m3 = -1e30f;
    float s = 0.f;
    int base = row0 * (NCOLS / 4) + t;
#pragma unroll 4
    for (int r = 0; r < 64; r++) {
        float4 v = p[base + r * (NCOLS / 4)];
        s += (v.x + v.y) + (v.z + v.w);
        m0 = fmaxf(m0, v.x); m1 = fmaxf(m1, v.y);
        m2 = fmaxf(m2, v.z); m3 = fmaxf(m3, v.w);
    }
    atomicMax(&g_colmax[4 * t + 0], __float_as_int(m0));
    atomicMax(&g_colmax[4 * t + 1], __float_as_int(m1));
    atomicMax(&g_colmax[4 * t + 2], __float_as_int(m2));
    atomicMax(&g_colmax[4 * t + 3], __float_as_int(m3));

    // block reduce the sum: fp32 within warp, double across warps
    for (int o = 16; o; o >>= 1) s += __shfl_down_sync(0xffffffffu, s, o);
    __shared__ float ws[32];
    int lane = t & 31, w = t >> 5;
    if (lane == 0) ws[w] = s;
    __syncthreads();
    if (t < 32) {
        double d = (double)ws[t];
        for (int o = 16; o; o >>= 1) d += __shfl_down_sync(0xffffffffu, d, o);
        if (t == 0) atomicAdd(&g_sum, d);
    }
}

__global__ void k_mean() {
    if (threadIdx.x == 0 && blockIdx.x == 0)
        g_mean = (float)(g_sum / (double)((long long)NROWS * NCOLS));
}

// ---------------- kernel 2: per-column sum of exp(att - colmax) over att>mean ----------------
__global__ __launch_bounds__(1024) void k_stats2(const float* __restrict__ att) {
    const int t = threadIdx.x;
    const int row0 = blockIdx.x * 64;
    const float mean = g_mean;
    const float c0 = __int_as_float(g_colmax[4 * t + 0]);
    const float c1 = __int_as_float(g_colmax[4 * t + 1]);
    const float c2 = __int_as_float(g_colmax[4 * t + 2]);
    const float c3 = __int_as_float(g_colmax[4 * t + 3]);
    const float4* p = (const float4*)att;
    float s0 = 0.f, s1 = 0.f, s2 = 0.f, s3 = 0.f;
    int base = row0 * (NCOLS / 4) + t;
#pragma unroll 4
    for (int r = 0; r < 64; r++) {
        float4 v = p[base + r * (NCOLS / 4)];
        if (v.x > mean) s0 += __expf(v.x - c0);
        if (v.y > mean) s1 += __expf(v.y - c1);
        if (v.z > mean) s2 += __expf(v.z - c2);
        if (v.w > mean) s3 += __expf(v.w - c3);
    }
    atomicAdd(&g_colsum[4 * t + 0], s0);
    atomicAdd(&g_colsum[4 * t + 1], s1);
    atomicAdd(&g_colsum[4 * t + 2], s2);
    atomicAdd(&g_colsum[4 * t + 3], s3);
}

__global__ void k_scale() {
    int j = blockIdx.x * blockDim.x + threadIdx.x;
    if (j < NCOLS) {
        float s = g_colsum[j];
        g_colscale[j] = (s > 0.f) ? (2.5f / s) : 0.f;
    }
}

// ---------------- kernel 3: h = x @ W^T, stored transposed [f][n], tf32-rounded ----------------
__global__ __launch_bounds__(128) void k_h(const float* __restrict__ x,
                                           const float* __restrict__ W) {
    __shared__ float xs[16 * 512];   // 32 KB
    __shared__ float ws[128 * 17];   // 8.5 KB (chunk of 16 k, pad 17)
    const int t = threadIdx.x;       // = output feature f
    const int n0 = blockIdx.x * 16;

    const float4* xp = (const float4*)(x + n0 * 512);
    float4* xs4 = (float4*)xs;
    for (int i = t; i < 2048; i += 128) xs4[i] = xp[i];

    float acc[16];
#pragma unroll
    for (int n = 0; n < 16; n++) acc[n] = 0.f;

    for (int k0 = 0; k0 < 512; k0 += 16) {
        __syncthreads();
        for (int i = t; i < 128 * 16; i += 128) {
            int f = i >> 4, kk = i & 15;
            ws[f * 17 + kk] = W[f * 512 + k0 + kk];
        }
        __syncthreads();
#pragma unroll
        for (int kk = 0; kk < 16; kk++) {
            float w = ws[t * 17 + kk];
            int kg = k0 + kk;
#pragma unroll
            for (int n = 0; n < 16; n++)
                acc[n] = fmaf(xs[n * 512 + kg], w, acc[n]);
        }
    }
#pragma unroll
    for (int n = 0; n < 16; n++)
        g_hT[t * NCOLS + n0 + n] = to_tf32(acc[n]);
}

// ---------------- kernel 4: fused softmax-dropout GEMM (tf32 mma.sync) ----------------
// out[n, c*128+f] = sum_j a[c*4096+n, j] * h[j, f]
__device__ __forceinline__ float aconv(float att, unsigned keep, float mean,
                                       float cmax, float cscale) {
    float v = 0.f;
    if (keep && (att > mean)) v = __expf(att - cmax) * cscale;
    return to_tf32(v);
}

__global__ __launch_bounds__(256, 1) void k_gemm(const float* __restrict__ att,
                                                 const unsigned char* __restrict__ maskb,
                                                 float* __restrict__ out) {
    __shared__ float As[128][36];
    __shared__ float Bs[128][36];
    const int t = threadIdx.x;
    const int warp = t >> 5, lane = t & 31;
    const int lr = lane >> 2, lq = lane & 3;
    const int wy = warp >> 2, wx = warp & 3;   // 2 x 4 warp grid
    const int m0 = wy * 64, n0w = wx * 32;
    const int bm = blockIdx.x;
    const int mode = g_mask_mode;
    const float mean = g_mean;

    float acc[4][4][4];
#pragma unroll
    for (int a = 0; a < 4; a++)
#pragma unroll
        for (int b = 0; b < 4; b++)
#pragma unroll
            for (int c = 0; c < 4; c++) acc[a][b][c] = 0.f;

    const int rload = t >> 3;         // 0..31
    const int cb4 = (t & 7) * 4;      // 0,4,...,28
    const int rA = bm * 128 + rload;

    float4 ar[4]; unsigned mb[4]; float4 br[4];
    float4 cmv, csv;

    auto LOAD = [&](int it) {
        const int col = it * 32 + cb4;
#pragma unroll
        for (int p = 0; p < 4; p++) {
            int gi = (rA + p * 32) * NCOLS + col;
            ar[p] = *(const float4*)(att + gi);
            if (mode == 0) {
                int4 m = *(const int4*)((const int*)maskb + gi);
                mb[p] = (m.x ? 1u : 0u) | (m.y ? 2u : 0u) | (m.z ? 4u : 0u) | (m.w ? 8u : 0u);
            } else if (mode == 1) {
                unsigned mm = *(const unsigned*)(maskb + gi);
                mb[p] = ((mm & 0xffu) ? 1u : 0u) | ((mm & 0xff00u) ? 2u : 0u) |
                        ((mm & 0xff0000u) ? 4u : 0u) | ((mm & 0xff000000u) ? 8u : 0u);
            } else {
                float4 m = *(const float4*)((const float*)maskb + gi);
                mb[p] = (m.x != 0.f ? 1u : 0u) | (m.y != 0.f ? 2u : 0u) |
                        (m.z != 0.f ? 4u : 0u) | (m.w != 0.f ? 8u : 0u);
            }
            br[p] = *(const float4*)(g_hT + (rload + p * 32) * NCOLS + col);
        }
        int4 cmi = *(const int4*)&g_colmax[col];
        cmv = make_float4(__int_as_float(cmi.x), __int_as_float(cmi.y),
                          __int_as_float(cmi.z), __int_as_float(cmi.w));
        csv = *(const float4*)&g_colscale[col];
    };

    LOAD(0);
    for (int it = 0; it < NCOLS / 32; ++it) {
        __syncthreads();
#pragma unroll
        for (int p = 0; p < 4; p++)
            *(float4*)&Bs[rload + p * 32][cb4] = br[p];
#pragma unroll
        for (int p = 0; p < 4; p++) {
            float4 v = ar[p];
            float4 o;
            o.x = aconv(v.x, mb[p] & 1u, mean, cmv.x, csv.x);
            o.y = aconv(v.y, mb[p] & 2u, mean, cmv.y, csv.y);
            o.z = aconv(v.z, mb[p] & 4u, mean, cmv.z, csv.z);
            o.w = aconv(v.w, mb[p] & 8u, mean, cmv.w, csv.w);
            *(float4*)&As[rload + p * 32][cb4] = o;
        }
        __syncthreads();
        if (it + 1 < NCOLS / 32) LOAD(it + 1);   // prefetch overlaps MMA below
#pragma unroll
        for (int s = 0; s < 4; s++) {
            const int sk = s * 8;
            unsigned afr[4][4];
#pragma unroll
            for (int mi = 0; mi < 4; mi++) {
                int r = m0 + mi * 16;
                afr[mi][0] = __float_as_uint(As[r + lr][sk + lq]);
                afr[mi][1] = __float_as_uint(As[r + lr + 8][sk + lq]);
                afr[mi][2] = __float_as_uint(As[r + lr][sk + lq + 4]);
                afr[mi][3] = __float_as_uint(As[r + lr + 8][sk + lq + 4]);
            }
#pragma unroll
            for (int ni = 0; ni < 4; ni++) {
                unsigned b0 = __float_as_uint(Bs[n0w + ni * 8 + lr][sk + lq]);
                unsigned b1 = __float_as_uint(Bs[n0w + ni * 8 + lr][sk + lq + 4]);
#pragma unroll
                for (int mi = 0; mi < 4; mi++)
                    mma_tf32(acc[mi][ni], afr[mi], b0, b1);
            }
        }
    }

    // epilogue: i = c*4096 + n  ->  out[n*512 + c*128 + f]
#pragma unroll
    for (int mi = 0; mi < 4; mi++) {
        int i0 = bm * 128 + m0 + mi * 16 + lr;
        int i2 = i0 + 8;
#pragma unroll
        for (int ni = 0; ni < 4; ni++) {
            int f = n0w + ni * 8 + lq * 2;
            *(float2*)(out + (i0 & 4095) * 512 + (i0 >> 12) * 128 + f) =
                make_float2(acc[mi][ni][0], acc[mi][ni][1]);
            *(float2*)(out + (i2 & 4095) * 512 + (i2 >> 12) * 128 + f) =
                make_float2(acc[mi][ni][2], acc[mi][ni][3]);
        }
    }
}

// ---------------- launch ----------------
extern "C" void kernel_launch(void* const* d_in, const int* in_sizes, int n_in,
                              void* d_out, int out_size) {
    const float* x   = (const float*)d_in[0];
    const float* att = (const float*)d_in[1];
    const float* W   = (const float*)d_in[2];
    const unsigned char* mask = (const unsigned char*)d_in[3];
    float* out = (float*)d_out;

    k_init<<<16, 256>>>();
    k_detect<<<1, 256>>>(mask);
    k_stats1<<<NROWS / 64, 1024>>>(att);
    k_mean<<<1, 32>>>();
    k_stats2<<<NROWS / 64, 1024>>>(att);
    k_scale<<<16, 256>>>();
    k_h<<<NCOLS / 16, 128>>>(x, W);
    k_gemm<<<NROWS / 128, 256>>>(att, mask, out);
}

// round 10
// speedup vs baseline: 1.1981x; 1.1981x over previous
#include <cuda_runtime.h>
#include <cuda_fp16.h>
#include <cstdint>

#define NROWS 16384   // C*N
#define NCOLS 4096    // N
#define OUTF  128

// ---------------- device globals (scratch; no allocations allowed) ----------------
__device__ double g_sum;
__device__ int    g_colmax[NCOLS];            // float bits as int (attention >= 0)
__device__ float  g_colsum[NCOLS];
__device__ int    g_mask_mode;                // 0=int32, 1=uint8(bool), 2=float32
__device__ __half g_e[(size_t)NROWS * NCOLS]; // post-softmax+dropout attention, fp16 (128 MB)
__device__ __half g_hs[OUTF * NCOLS];         // (cscale_j * h[j][f]) stored f-major: [f][j]

// ---------------- helpers ----------------
__device__ __forceinline__ void mma_f16(float* c, const unsigned* a, unsigned b0, unsigned b1) {
    asm volatile(
        "mma.sync.aligned.m16n8k16.row.col.f32.f16.f16.f32 "
        "{%0,%1,%2,%3}, {%4,%5,%6,%7}, {%8,%9}, {%0,%1,%2,%3};\n"
        : "+f"(c[0]), "+f"(c[1]), "+f"(c[2]), "+f"(c[3])
        : "r"(a[0]), "r"(a[1]), "r"(a[2]), "r"(a[3]), "r"(b0), "r"(b1));
}

__device__ __forceinline__ unsigned smem_u32(const void* p) {
    unsigned a;
    asm("{ .reg .u64 t; cvta.to.shared.u64 t, %1; cvt.u32.u64 %0, t; }" : "=r"(a) : "l"(p));
    return a;
}

// ---------------- kernel 0: init + mask-dtype detection (merged) ----------------
__global__ void k_initdet(const unsigned char* __restrict__ m) {
    if (blockIdx.x == 16) {
        __shared__ int f1, f23;
        if (threadIdx.x == 0) { f1 = 0; f23 = 0; }
        __syncthreads();
        for (int i = threadIdx.x; i < 65536; i += blockDim.x) {
            if (m[i]) {
                int r = i & 3;
                if (r == 1) f1 = 1;
                else if (r >= 2) f23 = 1;
            }
        }
        __syncthreads();
        if (threadIdx.x == 0) g_mask_mode = f1 ? 1 : (f23 ? 2 : 0);
    } else {
        int id = blockIdx.x * blockDim.x + threadIdx.x;
        if (id < NCOLS) {
            g_colmax[id] = (int)0xFF800000;
            g_colsum[id] = 0.f;
        }
        if (id == 0) g_sum = 0.0;
    }
}

// ---------------- kernel 1: global sum (double-accurate) + per-column max ----------------
__global__ __launch_bounds__(1024) void k_stats1(const float* __restrict__ att) {
    const int t = threadIdx.x;
    const int row0 = blockIdx.x * 64;
    const float4* p = (const float4*)att;
    float m0 = -1e30f, m1 = -1e30f, m2 = -1e30f, m3 = -1e30f;
    float s = 0.f;
    int base = row0 * (NCOLS / 4) + t;
#pragma unroll 4
    for (int r = 0; r < 64; r++) {
        float4 v = p[base + r * (NCOLS / 4)];
        s += (v.x + v.y) + (v.z + v.w);
        m0 = fmaxf(m0, v.x); m1 = fmaxf(m1, v.y);
        m2 = fmaxf(m2, v.z); m3 = fmaxf(m3, v.w);
    }
    atomicMax(&g_colmax[4 * t + 0], __float_as_int(m0));
    atomicMax(&g_colmax[4 * t + 1], __float_as_int(m1));
    atomicMax(&g_colmax[4 * t + 2], __float_as_int(m2));
    atomicMax(&g_colmax[4 * t + 3], __float_as_int(m3));

    for (int o = 16; o; o >>= 1) s += __shfl_down_sync(0xffffffffu, s, o);
    __shared__ float ws[32];
    int lane = t & 31, w = t >> 5;
    if (lane == 0) ws[w] = s;
    __syncthreads();
    if (t < 32) {
        double d = (double)ws[t];
        for (int o = 16; o; o >>= 1) d += __shfl_down_sync(0xffffffffu, d, o);
        if (t == 0) atomicAdd(&g_sum, d);
    }
}

// ---------------- kernel 2: colsum of exp + materialize E = dropout(softmax-numer) fp16 ----------------
__global__ __launch_bounds__(1024) void k_stats2e(const float* __restrict__ att,
                                                  const unsigned char* __restrict__ maskb) {
    const int t = threadIdx.x;
    const int row0 = blockIdx.x * 64;
    const float mean = (float)(g_sum / (double)((long long)NROWS * NCOLS));
    const int mode = g_mask_mode;
    const float c0 = __int_as_float(g_colmax[4 * t + 0]);
    const float c1 = __int_as_float(g_colmax[4 * t + 1]);
    const float c2 = __int_as_float(g_colmax[4 * t + 2]);
    const float c3 = __int_as_float(g_colmax[4 * t + 3]);
    float s0 = 0.f, s1 = 0.f, s2 = 0.f, s3 = 0.f;

    for (int r = 0; r < 64; r++) {
        const int gi = (row0 + r) * NCOLS + 4 * t;
        float4 v = *(const float4*)(att + gi);
        // mask -> keep flags
        bool k0, k1, k2, k3;
        if (mode == 0) {
            int4 m = *(const int4*)((const int*)maskb + gi);
            k0 = m.x != 0; k1 = m.y != 0; k2 = m.z != 0; k3 = m.w != 0;
        } else if (mode == 1) {
            unsigned mm = *(const unsigned*)(maskb + gi);
            k0 = (mm & 0xffu) != 0; k1 = (mm & 0xff00u) != 0;
            k2 = (mm & 0xff0000u) != 0; k3 = (mm & 0xff000000u) != 0;
        } else {
            float4 m = *(const float4*)((const float*)maskb + gi);
            k0 = m.x != 0.f; k1 = m.y != 0.f; k2 = m.z != 0.f; k3 = m.w != 0.f;
        }
        float e0 = (v.x > mean) ? __expf(v.x - c0) : 0.f; s0 += e0;
        float e1 = (v.y > mean) ? __expf(v.y - c1) : 0.f; s1 += e1;
        float e2 = (v.z > mean) ? __expf(v.z - c2) : 0.f; s2 += e2;
        float e3 = (v.w > mean) ? __expf(v.w - c3) : 0.f; s3 += e3;
        union { __half2 h[2]; uint2 u; } pk;
        pk.h[0] = __floats2half2_rn(k0 ? e0 : 0.f, k1 ? e1 : 0.f);
        pk.h[1] = __floats2half2_rn(k2 ? e2 : 0.f, k3 ? e3 : 0.f);
        *(uint2*)(g_e + gi) = pk.u;
    }
    atomicAdd(&g_colsum[4 * t + 0], s0);
    atomicAdd(&g_colsum[4 * t + 1], s1);
    atomicAdd(&g_colsum[4 * t + 2], s2);
    atomicAdd(&g_colsum[4 * t + 3], s3);
}

// ---------------- kernel 3: Hs[f][j] = fp16( (2.5/colsum_j) * (x @ W^T)[j][f] ) ----------------
__global__ __launch_bounds__(128) void k_h(const float* __restrict__ x,
                                           const float* __restrict__ W) {
    __shared__ float xs[16 * 512];   // 32 KB
    __shared__ float ws[128 * 17];   // 8.5 KB
    const int t = threadIdx.x;       // = output feature f
    const int n0 = blockIdx.x * 16;

    const float4* xp = (const float4*)(x + n0 * 512);
    float4* xs4 = (float4*)xs;
    for (int i = t; i < 2048; i += 128) xs4[i] = xp[i];

    float acc[16];
#pragma unroll
    for (int n = 0; n < 16; n++) acc[n] = 0.f;

    for (int k0 = 0; k0 < 512; k0 += 16) {
        __syncthreads();
        for (int i = t; i < 128 * 16; i += 128) {
            int f = i >> 4, kk = i & 15;
            ws[f * 17 + kk] = W[f * 512 + k0 + kk];
        }
        __syncthreads();
#pragma unroll
        for (int kk = 0; kk < 16; kk++) {
            float w = ws[t * 17 + kk];
            int kg = k0 + kk;
#pragma unroll
            for (int n = 0; n < 16; n++)
                acc[n] = fmaf(xs[n * 512 + kg], w, acc[n]);
        }
    }
    // scale by per-node softmax denominator (dropout 1/(1-p)=2.5 folded in), store f-major fp16
    __half hv[16];
#pragma unroll
    for (int n = 0; n < 16; n++) {
        float cs = g_colsum[n0 + n];
        float sc = (cs > 0.f) ? (2.5f / cs) : 0.f;
        hv[n] = __float2half(sc * acc[n]);
    }
    *(uint4*)(g_hs + t * NCOLS + n0)     = *(uint4*)&hv[0];
    *(uint4*)(g_hs + t * NCOLS + n0 + 8) = *(uint4*)&hv[8];
}

// ---------------- kernel 4: pure fp16 GEMM  out = E[16384x4096] @ Hs^T[4096x128] ----------------
__global__ __launch_bounds__(256, 1) void k_gemm2(float* __restrict__ out) {
    __shared__ __half As[128 * 40];   // 128 rows x 32 halves, stride 40 (80B, 16B-aligned)
    __shared__ __half Bs[128 * 40];   // 128 f    x 32 halves, stride 40
    const int t = threadIdx.x;
    const int warp = t >> 5, lane = t & 31;
    const int lr = lane >> 2, lq = lane & 3;
    const int m0w = (warp >> 1) * 32;       // 4 warps along M
    const int n0w = (warp & 1) * 64;        // 2 warps along N
    const int bm = blockIdx.x;
    const int rl = t >> 2, seg = t & 3;     // loader mapping: 64 rows x 4 x 16B per pass

    float acc[2][8][4];
#pragma unroll
    for (int a = 0; a < 2; a++)
#pragma unroll
        for (int b = 0; b < 8; b++)
#pragma unroll
            for (int c = 0; c < 4; c++) acc[a][b][c] = 0.f;

    uint4 aP[2], bP[2];
    auto LOAD = [&](int it) {
        const int col = it * 32 + seg * 8;
        aP[0] = *(const uint4*)(g_e + (bm * 128 + rl) * NCOLS + col);
        aP[1] = *(const uint4*)(g_e + (bm * 128 + rl + 64) * NCOLS + col);
        bP[0] = *(const uint4*)(g_hs + rl * NCOLS + col);
        bP[1] = *(const uint4*)(g_hs + (rl + 64) * NCOLS + col);
    };

    // per-lane ldmatrix source row/col within the A tile
    const int arow = m0w + (lane & 7) + ((lane >> 3) & 1) * 8;
    const int acol = ((lane >> 4) & 1) * 8;
    const unsigned as_b = smem_u32(As);

    LOAD(0);
    for (int it = 0; it < NCOLS / 32; ++it) {
        __syncthreads();
        *(uint4*)&As[rl * 40 + seg * 8]        = aP[0];
        *(uint4*)&As[(rl + 64) * 40 + seg * 8] = aP[1];
        *(uint4*)&Bs[rl * 40 + seg * 8]        = bP[0];
        *(uint4*)&Bs[(rl + 64) * 40 + seg * 8] = bP[1];
        __syncthreads();
        if (it + 1 < NCOLS / 32) LOAD(it + 1);   // prefetch overlaps MMA

#pragma unroll
        for (int kk = 0; kk < 32; kk += 16) {
            unsigned a[2][4];
#pragma unroll
            for (int mi = 0; mi < 2; mi++) {
                unsigned addr = as_b + ((arow + mi * 16) * 40 + kk + acol) * 2;
                asm volatile("ldmatrix.sync.aligned.m8n8.x4.shared.b16 {%0,%1,%2,%3}, [%4];"
                             : "=r"(a[mi][0]), "=r"(a[mi][1]), "=r"(a[mi][2]), "=r"(a[mi][3])
                             : "r"(addr));
            }
#pragma unroll
            for (int ni = 0; ni < 8; ni++) {
                const int nrow = n0w + ni * 8 + lr;
                unsigned b0 = *(const unsigned*)&Bs[nrow * 40 + kk + 2 * lq];
                unsigned b1 = *(const unsigned*)&Bs[nrow * 40 + kk + 2 * lq + 8];
                mma_f16(acc[0][ni], a[0], b0, b1);
                mma_f16(acc[1][ni], a[1], b0, b1);
            }
        }
    }

    // epilogue: global row i = c*4096 + n  ->  out[n*512 + c*128 + f]
#pragma unroll
    for (int mi = 0; mi < 2; mi++) {
        int i0 = bm * 128 + m0w + mi * 16 + lr;
        int i2 = i0 + 8;
#pragma unroll
        for (int ni = 0; ni < 8; ni++) {
            int f = n0w + ni * 8 + 2 * lq;
            *(float2*)(out + (i0 & 4095) * 512 + (i0 >> 12) * 128 + f) =
                make_float2(acc[mi][ni][0], acc[mi][ni][1]);
            *(float2*)(out + (i2 & 4095) * 512 + (i2 >> 12) * 128 + f) =
                make_float2(acc[mi][ni][2], acc[mi][ni][3]);
        }
    }
}

// ---------------- launch ----------------
extern "C" void kernel_launch(void* const* d_in, const int* in_sizes, int n_in,
                              void* d_out, int out_size) {
    const float* x   = (const float*)d_in[0];
    const float* att = (const float*)d_in[1];
    const float* W   = (const float*)d_in[2];
    const unsigned char* mask = (const unsigned char*)d_in[3];
    float* out = (float*)d_out;

    k_initdet<<<17, 256>>>(mask);
    k_stats1<<<NROWS / 64, 1024>>>(att);
    k_stats2e<<<NROWS / 64, 1024>>>(att, mask);
    k_h<<<NCOLS / 16, 128>>>(x, W);
    k_gemm2<<<NROWS / 128, 256>>>(out);
}

// round 11
// speedup vs baseline: 1.3959x; 1.1650x over previous
#include <cuda_runtime.h>
#include <cuda_fp16.h>
#include <cstdint>

#define NROWS 16384   // C*N
#define NCOLS 4096    // N
#define OUTF  128

// ---------------- device globals (scratch; no allocations allowed) ----------------
__device__ double g_sum;
__device__ int    g_colmax[NCOLS];            // float bits as int (attention >= 0)
__device__ float  g_colsum[NCOLS];
__device__ int    g_mask_mode;                // 0=int32, 1=uint8(bool), 2=float32
__device__ __half g_e[(size_t)NROWS * NCOLS]; // post-softmax+dropout attention, fp16 (128 MB)
__device__ __half g_hs[OUTF * NCOLS];         // (cscale_j * h[j][f]) stored f-major: [f][j]

// ---------------- helpers ----------------
__device__ __forceinline__ float to_tf32(float x) {
    unsigned u;
    asm("cvt.rna.tf32.f32 %0, %1;" : "=r"(u) : "f"(x));
    return __uint_as_float(u);
}

__device__ __forceinline__ void mma_f16(float* c, const unsigned* a, unsigned b0, unsigned b1) {
    asm volatile(
        "mma.sync.aligned.m16n8k16.row.col.f32.f16.f16.f32 "
        "{%0,%1,%2,%3}, {%4,%5,%6,%7}, {%8,%9}, {%0,%1,%2,%3};\n"
        : "+f"(c[0]), "+f"(c[1]), "+f"(c[2]), "+f"(c[3])
        : "r"(a[0]), "r"(a[1]), "r"(a[2]), "r"(a[3]), "r"(b0), "r"(b1));
}

__device__ __forceinline__ void mma_tf32(float* c, const unsigned* a, unsigned b0, unsigned b1) {
    asm volatile(
        "mma.sync.aligned.m16n8k8.row.col.f32.tf32.tf32.f32 "
        "{%0,%1,%2,%3}, {%4,%5,%6,%7}, {%8,%9}, {%0,%1,%2,%3};\n"
        : "+f"(c[0]), "+f"(c[1]), "+f"(c[2]), "+f"(c[3])
        : "r"(a[0]), "r"(a[1]), "r"(a[2]), "r"(a[3]), "r"(b0), "r"(b1));
}

__device__ __forceinline__ unsigned smem_u32(const void* p) {
    unsigned a;
    asm("{ .reg .u64 t; cvta.to.shared.u64 t, %1; cvt.u32.u64 %0, t; }" : "=r"(a) : "l"(p));
    return a;
}

#define CP16(dst, src) \
    asm volatile("cp.async.cg.shared.global [%0], [%1], 16;" :: "r"(dst), \
                 "l"(__cvta_generic_to_global(src)))
#define CP_COMMIT() asm volatile("cp.async.commit_group;" ::: "memory")
#define CP_WAIT1()  asm volatile("cp.async.wait_group 1;" ::: "memory")

// ---------------- kernel 0: init + mask-dtype detection (merged) ----------------
__global__ void k_initdet(const unsigned char* __restrict__ m) {
    if (blockIdx.x == 16) {
        __shared__ int f1, f23;
        if (threadIdx.x == 0) { f1 = 0; f23 = 0; }
        __syncthreads();
        for (int i = threadIdx.x; i < 65536; i += blockDim.x) {
            if (m[i]) {
                int r = i & 3;
                if (r == 1) f1 = 1;
                else if (r >= 2) f23 = 1;
            }
        }
        __syncthreads();
        if (threadIdx.x == 0) g_mask_mode = f1 ? 1 : (f23 ? 2 : 0);
    } else {
        int id = blockIdx.x * blockDim.x + threadIdx.x;
        if (id < NCOLS) {
            g_colmax[id] = (int)0xFF800000;
            g_colsum[id] = 0.f;
        }
        if (id == 0) g_sum = 0.0;
    }
}

// ---------------- kernel 1: global sum (double-accurate) + per-column max ----------------
__global__ __launch_bounds__(1024) void k_stats1(const float* __restrict__ att) {
    const int t = threadIdx.x;
    const int row0 = blockIdx.x * 64;
    const float4* p = (const float4*)att;
    float m0 = -1e30f, m1 = -1e30f, m2 = -1e30f, m3 = -1e30f;
    float s = 0.f;
    int base = row0 * (NCOLS / 4) + t;
#pragma unroll 4
    for (int r = 0; r < 64; r++) {
        float4 v = p[base + r * (NCOLS / 4)];
        s += (v.x + v.y) + (v.z + v.w);
        m0 = fmaxf(m0, v.x); m1 = fmaxf(m1, v.y);
        m2 = fmaxf(m2, v.z); m3 = fmaxf(m3, v.w);
    }
    atomicMax(&g_colmax[4 * t + 0], __float_as_int(m0));
    atomicMax(&g_colmax[4 * t + 1], __float_as_int(m1));
    atomicMax(&g_colmax[4 * t + 2], __float_as_int(m2));
    atomicMax(&g_colmax[4 * t + 3], __float_as_int(m3));

    for (int o = 16; o; o >>= 1) s += __shfl_down_sync(0xffffffffu, s, o);
    __shared__ float ws[32];
    int lane = t & 31, w = t >> 5;
    if (lane == 0) ws[w] = s;
    __syncthreads();
    if (t < 32) {
        double d = (double)ws[t];
        for (int o = 16; o; o >>= 1) d += __shfl_down_sync(0xffffffffu, d, o);
        if (t == 0) atomicAdd(&g_sum, d);
    }
}

// ---------------- kernel 2: colsum of exp + materialize E = dropout(softmax-numer) fp16 ----------------
__global__ __launch_bounds__(1024) void k_stats2e(const float* __restrict__ att,
                                                  const unsigned char* __restrict__ maskb) {
    const int t = threadIdx.x;
    const int row0 = blockIdx.x * 64;
    const float mean = (float)(g_sum / (double)((long long)NROWS * NCOLS));
    const int mode = g_mask_mode;
    const float c0 = __int_as_float(g_colmax[4 * t + 0]);
    const float c1 = __int_as_float(g_colmax[4 * t + 1]);
    const float c2 = __int_as_float(g_colmax[4 * t + 2]);
    const float c3 = __int_as_float(g_colmax[4 * t + 3]);
    float s0 = 0.f, s1 = 0.f, s2 = 0.f, s3 = 0.f;

    for (int r = 0; r < 64; r++) {
        const int gi = (row0 + r) * NCOLS + 4 * t;
        float4 v = *(const float4*)(att + gi);
        bool k0, k1, k2, k3;
        if (mode == 0) {
            int4 m = *(const int4*)((const int*)maskb + gi);
            k0 = m.x != 0; k1 = m.y != 0; k2 = m.z != 0; k3 = m.w != 0;
        } else if (mode == 1) {
            unsigned mm = *(const unsigned*)(maskb + gi);
            k0 = (mm & 0xffu) != 0; k1 = (mm & 0xff00u) != 0;
            k2 = (mm & 0xff0000u) != 0; k3 = (mm & 0xff000000u) != 0;
        } else {
            float4 m = *(const float4*)((const float*)maskb + gi);
            k0 = m.x != 0.f; k1 = m.y != 0.f; k2 = m.z != 0.f; k3 = m.w != 0.f;
        }
        float e0 = (v.x > mean) ? __expf(v.x - c0) : 0.f; s0 += e0;
        float e1 = (v.y > mean) ? __expf(v.y - c1) : 0.f; s1 += e1;
        float e2 = (v.z > mean) ? __expf(v.z - c2) : 0.f; s2 += e2;
        float e3 = (v.w > mean) ? __expf(v.w - c3) : 0.f; s3 += e3;
        union { __half2 h[2]; uint2 u; } pk;
        pk.h[0] = __floats2half2_rn(k0 ? e0 : 0.f, k1 ? e1 : 0.f);
        pk.h[1] = __floats2half2_rn(k2 ? e2 : 0.f, k3 ? e3 : 0.f);
        __stcs((uint2*)(g_e + gi), pk.u);   // streaming store: don't pollute L2
    }
    atomicAdd(&g_colsum[4 * t + 0], s0);
    atomicAdd(&g_colsum[4 * t + 1], s1);
    atomicAdd(&g_colsum[4 * t + 2], s2);
    atomicAdd(&g_colsum[4 * t + 3], s3);
}

// ---------------- kernel 3: tf32 MMA  h = x @ W^T, scaled, stored f-major fp16 ----------------
// CTA: 64 nodes x 128 features, 256 threads, K-chunk 32 (16 iters over K=512)
__global__ __launch_bounds__(256) void k_h(const float* __restrict__ x,
                                           const float* __restrict__ W) {
    __shared__ float As[64 * 36];    // x tile  [node][k]  (pad 36)
    __shared__ float Bs[128 * 36];   // W tile  [f][k]
    const int t = threadIdx.x;
    const int warp = t >> 5, lane = t & 31;
    const int lr = lane >> 2, lq = lane & 3;
    const int m0w = (warp >> 2) * 32;       // 2 warps along M(nodes)
    const int n0w = (warp & 3) * 32;        // 4 warps along N(features)
    const int bm = blockIdx.x;              // 64 blocks of 64 nodes
    const int rl = t >> 2, seg = t & 3;     // A loader: row rl, cols seg*8
    const int rb = t >> 1, cb = (t & 1) * 16; // B loader: row rb, cols cb..cb+15

    float acc[2][4][4];
#pragma unroll
    for (int a = 0; a < 2; a++)
#pragma unroll
        for (int b = 0; b < 4; b++)
#pragma unroll
            for (int c = 0; c < 4; c++) acc[a][b][c] = 0.f;

    float4 aP[2], bP[4];
    auto LOAD = [&](int it) {
        const int k0 = it * 32;
        const float* xp = x + (bm * 64 + rl) * 512 + k0 + seg * 8;
        aP[0] = *(const float4*)xp;
        aP[1] = *(const float4*)(xp + 4);
        const float* wp = W + rb * 512 + k0 + cb;
        bP[0] = *(const float4*)wp;       bP[1] = *(const float4*)(wp + 4);
        bP[2] = *(const float4*)(wp + 8); bP[3] = *(const float4*)(wp + 12);
    };

    LOAD(0);
    for (int it = 0; it < 16; ++it) {
        __syncthreads();
        {
            float av[8] = {aP[0].x, aP[0].y, aP[0].z, aP[0].w,
                           aP[1].x, aP[1].y, aP[1].z, aP[1].w};
            float* ad = As + rl * 36 + seg * 8;
#pragma unroll
            for (int i = 0; i < 8; i++) ad[i] = to_tf32(av[i]);
            float bv[16] = {bP[0].x, bP[0].y, bP[0].z, bP[0].w,
                            bP[1].x, bP[1].y, bP[1].z, bP[1].w,
                            bP[2].x, bP[2].y, bP[2].z, bP[2].w,
                            bP[3].x, bP[3].y, bP[3].z, bP[3].w};
            float* bd = Bs + rb * 36 + cb;
#pragma unroll
            for (int i = 0; i < 16; i++) bd[i] = to_tf32(bv[i]);
        }
        __syncthreads();
        if (it + 1 < 16) LOAD(it + 1);

#pragma unroll
        for (int s = 0; s < 4; s++) {
            const int sk = s * 8;
            unsigned a[2][4];
#pragma unroll
            for (int mi = 0; mi < 2; mi++) {
                int r = m0w + mi * 16;
                a[mi][0] = __float_as_uint(As[(r + lr) * 36 + sk + lq]);
                a[mi][1] = __float_as_uint(As[(r + lr + 8) * 36 + sk + lq]);
                a[mi][2] = __float_as_uint(As[(r + lr) * 36 + sk + lq + 4]);
                a[mi][3] = __float_as_uint(As[(r + lr + 8) * 36 + sk + lq + 4]);
            }
#pragma unroll
            for (int ni = 0; ni < 4; ni++) {
                int nrow = n0w + ni * 8 + lr;
                unsigned b0 = __float_as_uint(Bs[nrow * 36 + sk + lq]);
                unsigned b1 = __float_as_uint(Bs[nrow * 36 + sk + lq + 4]);
                mma_tf32(acc[0][ni], a[0], b0, b1);
                mma_tf32(acc[1][ni], a[1], b0, b1);
            }
        }
    }

    // epilogue: scale by 2.5/colsum[node], store fp16 f-major g_hs[f][n]
#pragma unroll
    for (int mi = 0; mi < 2; mi++) {
        int n1 = bm * 64 + m0w + mi * 16 + lr;
        int n2 = n1 + 8;
        float v1 = g_colsum[n1], v2 = g_colsum[n2];
        float cs1 = (v1 > 0.f) ? (2.5f / v1) : 0.f;
        float cs2 = (v2 > 0.f) ? (2.5f / v2) : 0.f;
#pragma unroll
        for (int ni = 0; ni < 4; ni++) {
            int f = n0w + ni * 8 + 2 * lq;
            g_hs[f * NCOLS + n1]       = __float2half(cs1 * acc[mi][ni][0]);
            g_hs[(f + 1) * NCOLS + n1] = __float2half(cs1 * acc[mi][ni][1]);
            g_hs[f * NCOLS + n2]       = __float2half(cs2 * acc[mi][ni][2]);
            g_hs[(f + 1) * NCOLS + n2] = __float2half(cs2 * acc[mi][ni][3]);
        }
    }
}

// ---------------- kernel 4: fp16 GEMM  out = E[16384x4096] @ Hs^T, cp.async 3-stage ----------------
// CTA: M tile 64, N = 128, K-chunk 32; 256 CTAs, 256 threads
#define GSTG_A (64 * 40)    // halves per A stage
#define GSTG_B (128 * 40)   // halves per B stage
__global__ __launch_bounds__(256, 2) void k_gemm2(float* __restrict__ out) {
    __shared__ __half As[3 * GSTG_A];   // 15 KB
    __shared__ __half Bs[3 * GSTG_B];   // 30 KB
    const int t = threadIdx.x;
    const int warp = t >> 5, lane = t & 31;
    const int lr = lane >> 2, lq = lane & 3;
    const int m0w = (warp >> 2) * 32;       // 2 warps along M
    const int n0w = (warp & 3) * 32;        // 4 warps along N
    const int bm = blockIdx.x;
    const int rl = t >> 2, seg = t & 3;     // A loader: row rl (0..63), cols seg*8
    const int rb = t >> 1, cbh = (t & 1) * 16; // B loader: row rb (0..127), cols cbh, cbh+8

    float acc[2][4][4];
#pragma unroll
    for (int a = 0; a < 2; a++)
#pragma unroll
        for (int b = 0; b < 4; b++)
#pragma unroll
            for (int c = 0; c < 4; c++) acc[a][b][c] = 0.f;

    const unsigned as0 = smem_u32(As), bs0 = smem_u32(Bs);
    const unsigned a_dst = as0 + (rl * 40 + seg * 8) * 2;
    const unsigned b_dst = bs0 + (rb * 40 + cbh) * 2;
    const __half* a_src = g_e + (size_t)(bm * 64 + rl) * NCOLS + seg * 8;
    const __half* b_src = g_hs + rb * NCOLS + cbh;

    auto ISSUE = [&](int it) {
        const int st = it % 3;
        const int col = it * 32;
        CP16(a_dst + st * GSTG_A * 2, a_src + col);
        CP16(b_dst + st * GSTG_B * 2, b_src + col);
        CP16(b_dst + st * GSTG_B * 2 + 16, b_src + col + 8);
    };
    ISSUE(0); CP_COMMIT();
    ISSUE(1); CP_COMMIT();

    const int arow = m0w + (lane & 7) + ((lane >> 3) & 1) * 8;
    const int acol = ((lane >> 4) & 1) * 8;

    for (int it = 0; it < NCOLS / 32; ++it) {
        CP_WAIT1();
        __syncthreads();
        if (it + 2 < NCOLS / 32) ISSUE(it + 2);
        CP_COMMIT();

        const int st = it % 3;
        const unsigned asb = as0 + st * GSTG_A * 2;
        const __half* bsp = Bs + st * GSTG_B;
#pragma unroll
        for (int kk = 0; kk < 32; kk += 16) {
            unsigned a[2][4];
#pragma unroll
            for (int mi = 0; mi < 2; mi++) {
                unsigned addr = asb + ((arow + mi * 16) * 40 + kk + acol) * 2;
                asm volatile("ldmatrix.sync.aligned.m8n8.x4.shared.b16 {%0,%1,%2,%3}, [%4];"
                             : "=r"(a[mi][0]), "=r"(a[mi][1]), "=r"(a[mi][2]), "=r"(a[mi][3])
                             : "r"(addr));
            }
#pragma unroll
            for (int ni = 0; ni < 4; ni++) {
                const int nrow = n0w + ni * 8 + lr;
                unsigned b0 = *(const unsigned*)&bsp[nrow * 40 + kk + 2 * lq];
                unsigned b1 = *(const unsigned*)&bsp[nrow * 40 + kk + 2 * lq + 8];
                mma_f16(acc[0][ni], a[0], b0, b1);
                mma_f16(acc[1][ni], a[1], b0, b1);
            }
        }
    }

    // epilogue: global row i = c*4096 + n  ->  out[n*512 + c*128 + f]
#pragma unroll
    for (int mi = 0; mi < 2; mi++) {
        int i0 = bm * 64 + m0w + mi * 16 + lr;
        int i2 = i0 + 8;
#pragma unroll
        for (int ni = 0; ni < 4; ni++) {
            int f = n0w + ni * 8 + 2 * lq;
            *(float2*)(out + (i0 & 4095) * 512 + (i0 >> 12) * 128 + f) =
                make_float2(acc[mi][ni][0], acc[mi][ni][1]);
            *(float2*)(out + (i2 & 4095) * 512 + (i2 >> 12) * 128 + f) =
                make_float2(acc[mi][ni][2], acc[mi][ni][3]);
        }
    }
}

// ---------------- launch ----------------
extern "C" void kernel_launch(void* const* d_in, const int* in_sizes, int n_in,
                              void* d_out, int out_size) {
    const float* x   = (const float*)d_in[0];
    const float* att = (const float*)d_in[1];
    const float* W   = (const float*)d_in[2];
    const unsigned char* mask = (const unsigned char*)d_in[3];
    float* out = (float*)d_out;

    k_initdet<<<17, 256>>>(mask);
    k_stats1<<<NROWS / 64, 1024>>>(att);
    k_stats2e<<<NROWS / 64, 1024>>>(att, mask);
    k_h<<<NCOLS / 64, 256>>>(x, W);
    k_gemm2<<<NROWS / 64, 256>>>(out);
}

// round 15
// speedup vs baseline: 1.5351x; 1.0998x over previous
#include <cuda_runtime.h>
#include <cuda_fp16.h>
#include <cstdint>

#define NROWS 16384   // C*N
#define NCOLS 4096    // N
#define OUTF  128

// ---------------- device globals (scratch; no allocations allowed) ----------------
__device__ double g_sum;
__device__ int    g_colmax[NCOLS];            // float bits as int (attention >= 0)
__device__ float  g_colsum[NCOLS];
__device__ int    g_mask_mode;                // 0=int32, 1=uint8(bool), 2=float32
__device__ __half g_e[(size_t)NROWS * NCOLS]; // post-softmax+dropout attention, fp16 (128 MB)
__device__ __half g_hs[OUTF * NCOLS];         // (cscale_j * h[j][f]) stored f-major: [f][j]

// ---------------- helpers ----------------
__device__ __forceinline__ float to_tf32(float x) {
    unsigned u;
    asm("cvt.rna.tf32.f32 %0, %1;" : "=r"(u) : "f"(x));
    return __uint_as_float(u);
}

__device__ __forceinline__ void mma_f16(float* c, const unsigned* a, unsigned b0, unsigned b1) {
    asm volatile(
        "mma.sync.aligned.m16n8k16.row.col.f32.f16.f16.f32 "
        "{%0,%1,%2,%3}, {%4,%5,%6,%7}, {%8,%9}, {%0,%1,%2,%3};\n"
        : "+f"(c[0]), "+f"(c[1]), "+f"(c[2]), "+f"(c[3])
        : "r"(a[0]), "r"(a[1]), "r"(a[2]), "r"(a[3]), "r"(b0), "r"(b1));
}

__device__ __forceinline__ void mma_tf32(float* c, const unsigned* a, unsigned b0, unsigned b1) {
    asm volatile(
        "mma.sync.aligned.m16n8k8.row.col.f32.tf32.tf32.f32 "
        "{%0,%1,%2,%3}, {%4,%5,%6,%7}, {%8,%9}, {%0,%1,%2,%3};\n"
        : "+f"(c[0]), "+f"(c[1]), "+f"(c[2]), "+f"(c[3])
        : "r"(a[0]), "r"(a[1]), "r"(a[2]), "r"(a[3]), "r"(b0), "r"(b1));
}

__device__ __forceinline__ unsigned smem_u32(const void* p) {
    unsigned a;
    asm("{ .reg .u64 t; cvta.to.shared.u64 t, %1; cvt.u32.u64 %0, t; }" : "=r"(a) : "l"(p));
    return a;
}

#define CP16(dst, src) \
    asm volatile("cp.async.cg.shared.global [%0], [%1], 16;" :: "r"(dst), \
                 "l"(__cvta_generic_to_global(src)))
#define CP_COMMIT() asm volatile("cp.async.commit_group;" ::: "memory")
#define CP_WAIT1()  asm volatile("cp.async.wait_group 1;" ::: "memory")

// ---------------- kernel 0: init + mask-dtype detection (merged) ----------------
// detect: byte-lane fingerprint of first 16 KB via uint4 (u8 mask -> nonzero at
// ofs%4==1; f32 mask -> nonzero only at ofs%4 in {2,3}; i32 -> only ofs%4==0)
__global__ void k_initdet(const unsigned char* __restrict__ m) {
    if (blockIdx.x == 16) {
        __shared__ unsigned s1, s23;
        if (threadIdx.x == 0) { s1 = 0; s23 = 0; }
        __syncthreads();
        const uint4* p = (const uint4*)m;
        unsigned o1 = 0, o23 = 0;
#pragma unroll
        for (int i = threadIdx.x; i < 1024; i += 256) {   // 1024 * 16B = 16 KB
            uint4 v = p[i];
            unsigned w = v.x | 0u;
            o1  |= (v.x & 0xff00u) | (v.y & 0xff00u) | (v.z & 0xff00u) | (v.w & 0xff00u);
            o23 |= (v.x & 0xffff0000u) | (v.y & 0xffff0000u) |
                   (v.z & 0xffff0000u) | (v.w & 0xffff0000u);
            (void)w;
        }
        if (o1)  atomicOr(&s1, 1u);
        if (o23) atomicOr(&s23, 1u);
        __syncthreads();
        if (threadIdx.x == 0) g_mask_mode = s1 ? 1 : (s23 ? 2 : 0);
    } else {
        int id = blockIdx.x * blockDim.x + threadIdx.x;
        if (id < NCOLS) {
            g_colmax[id] = (int)0xFF800000;
            g_colsum[id] = 0.f;
        }
        if (id == 0) g_sum = 0.0;
    }
}

// ---------------- kernel 1: global sum (double-accurate) + per-column max ----------------
__global__ __launch_bounds__(1024) void k_stats1(const float* __restrict__ att) {
    const int t = threadIdx.x;
    const int row0 = blockIdx.x * 64;
    const float4* p = (const float4*)att;
    float m0 = -1e30f, m1 = -1e30f, m2 = -1e30f, m3 = -1e30f;
    float s = 0.f;
    int base = row0 * (NCOLS / 4) + t;
#pragma unroll 4
    for (int r = 0; r < 64; r++) {
        float4 v = p[base + r * (NCOLS / 4)];
        s += (v.x + v.y) + (v.z + v.w);
        m0 = fmaxf(m0, v.x); m1 = fmaxf(m1, v.y);
        m2 = fmaxf(m2, v.z); m3 = fmaxf(m3, v.w);
    }
    atomicMax(&g_colmax[4 * t + 0], __float_as_int(m0));
    atomicMax(&g_colmax[4 * t + 1], __float_as_int(m1));
    atomicMax(&g_colmax[4 * t + 2], __float_as_int(m2));
    atomicMax(&g_colmax[4 * t + 3], __float_as_int(m3));

    for (int o = 16; o; o >>= 1) s += __shfl_down_sync(0xffffffffu, s, o);
    __shared__ float ws[32];
    int lane = t & 31, w = t >> 5;
    if (lane == 0) ws[w] = s;
    __syncthreads();
    if (t < 32) {
        double d = (double)ws[t];
        for (int o = 16; o; o >>= 1) d += __shfl_down_sync(0xffffffffu, d, o);
        if (t == 0) atomicAdd(&g_sum, d);
    }
}

// ---------------- kernel 2: colsum of exp + materialize E = dropout(softmax-numer) fp16 ----------------
__global__ __launch_bounds__(1024) void k_stats2e(const float* __restrict__ att,
                                                  const unsigned char* __restrict__ maskb) {
    const int t = threadIdx.x;
    const int row0 = blockIdx.x * 64;
    const float mean = (float)(g_sum / (double)((long long)NROWS * NCOLS));
    const int mode = g_mask_mode;
    const float c0 = __int_as_float(g_colmax[4 * t + 0]);
    const float c1 = __int_as_float(g_colmax[4 * t + 1]);
    const float c2 = __int_as_float(g_colmax[4 * t + 2]);
    const float c3 = __int_as_float(g_colmax[4 * t + 3]);
    float s0 = 0.f, s1 = 0.f, s2 = 0.f, s3 = 0.f;

#pragma unroll 4
    for (int r = 0; r < 64; r++) {
        const int gi = (row0 + r) * NCOLS + 4 * t;
        float4 v = *(const float4*)(att + gi);
        bool k0, k1, k2, k3;
        if (mode == 0) {
            int4 m = *(const int4*)((const int*)maskb + gi);
            k0 = m.x != 0; k1 = m.y != 0; k2 = m.z != 0; k3 = m.w != 0;
        } else if (mode == 1) {
            unsigned mm = *(const unsigned*)(maskb + gi);
            k0 = (mm & 0xffu) != 0; k1 = (mm & 0xff00u) != 0;
            k2 = (mm & 0xff0000u) != 0; k3 = (mm & 0xff000000u) != 0;
        } else {
            float4 m = *(const float4*)((const float*)maskb + gi);
            k0 = m.x != 0.f; k1 = m.y != 0.f; k2 = m.z != 0.f; k3 = m.w != 0.f;
        }
        float e0 = (v.x > mean) ? __expf(v.x - c0) : 0.f; s0 += e0;
        float e1 = (v.y > mean) ? __expf(v.y - c1) : 0.f; s1 += e1;
        float e2 = (v.z > mean) ? __expf(v.z - c2) : 0.f; s2 += e2;
        float e3 = (v.w > mean) ? __expf(v.w - c3) : 0.f; s3 += e3;
        union { __half2 h[2]; uint2 u; } pk;
        pk.h[0] = __floats2half2_rn(k0 ? e0 : 0.f, k1 ? e1 : 0.f);
        pk.h[1] = __floats2half2_rn(k2 ? e2 : 0.f, k3 ? e3 : 0.f);
        __stcs((uint2*)(g_e + gi), pk.u);   // streaming store: don't pollute L2
    }
    atomicAdd(&g_colsum[4 * t + 0], s0);
    atomicAdd(&g_colsum[4 * t + 1], s1);
    atomicAdd(&g_colsum[4 * t + 2], s2);
    atomicAdd(&g_colsum[4 * t + 3], s3);
}

// ---------------- kernel 3: tf32 MMA  h = x @ W^T, scaled, stored f-major fp16 ----------------
// CTA: 16 nodes x 128 features, 256 threads, K-chunk 32 (16 iters over K=512); 256 CTAs
__global__ __launch_bounds__(256) void k_h(const float* __restrict__ x,
                                           const float* __restrict__ W) {
    __shared__ float As[16 * 36];    // x tile  [node][k]  (pad 36)
    __shared__ float Bs[128 * 36];   // W tile  [f][k]
    const int t = threadIdx.x;
    const int warp = t >> 5, lane = t & 31;
    const int lr = lane >> 2, lq = lane & 3;
    const int n0w = warp * 16;              // 8 warps along N(features)
    const int bm = blockIdx.x;              // 256 blocks of 16 nodes
    const int rl = t >> 3, seg = t & 7;     // A loader (threads 0-127): row rl, cols seg*4
    const int rb = t >> 1, cb = (t & 1) * 16; // B loader: row rb, cols cb..cb+15

    float acc[2][4];
#pragma unroll
    for (int b = 0; b < 2; b++)
#pragma unroll
        for (int c = 0; c < 4; c++) acc[b][c] = 0.f;

    float4 aP; float4 bP[4];
    auto LOAD = [&](int it) {
        const int k0 = it * 32;
        if (t < 128)
            aP = *(const float4*)(x + (bm * 16 + rl) * 512 + k0 + seg * 4);
        const float* wp = W + rb * 512 + k0 + cb;
        bP[0] = *(const float4*)wp;       bP[1] = *(const float4*)(wp + 4);
        bP[2] = *(const float4*)(wp + 8); bP[3] = *(const float4*)(wp + 12);
    };

    LOAD(0);
    for (int it = 0; it < 16; ++it) {
        __syncthreads();
        if (t < 128) {
            float* ad = As + rl * 36 + seg * 4;
            ad[0] = to_tf32(aP.x); ad[1] = to_tf32(aP.y);
            ad[2] = to_tf32(aP.z); ad[3] = to_tf32(aP.w);
        }
        {
            float bv[16] = {bP[0].x, bP[0].y, bP[0].z, bP[0].w,
                            bP[1].x, bP[1].y, bP[1].z, bP[1].w,
                            bP[2].x, bP[2].y, bP[2].z, bP[2].w,
                            bP[3].x, bP[3].y, bP[3].z, bP[3].w};
            float* bd = Bs + rb * 36 + cb;
#pragma unroll
            for (int i = 0; i < 16; i++) bd[i] = to_tf32(bv[i]);
        }
        __syncthreads();
        if (it + 1 < 16) LOAD(it + 1);

#pragma unroll
        for (int s = 0; s < 4; s++) {
            const int sk = s * 8;
            unsigned a[4];
            a[0] = __float_as_uint(As[lr * 36 + sk + lq]);
            a[1] = __float_as_uint(As[(lr + 8) * 36 + sk + lq]);
            a[2] = __float_as_uint(As[lr * 36 + sk + lq + 4]);
            a[3] = __float_as_uint(As[(lr + 8) * 36 + sk + lq + 4]);
#pragma unroll
            for (int ni = 0; ni < 2; ni++) {
                int nrow = n0w + ni * 8 + lr;
                unsigned b0 = __float_as_uint(Bs[nrow * 36 + sk + lq]);
                unsigned b1 = __float_as_uint(Bs[nrow * 36 + sk + lq + 4]);
                mma_tf32(acc[ni], a, b0, b1);
            }
        }
    }

    // epilogue: scale by 2.5/colsum[node], store fp16 f-major g_hs[f][n]
    {
        int n1 = bm * 16 + lr;
        int n2 = n1 + 8;
        float v1 = g_colsum[n1], v2 = g_colsum[n2];
        float cs1 = (v1 > 0.f) ? (2.5f / v1) : 0.f;
        float cs2 = (v2 > 0.f) ? (2.5f / v2) : 0.f;
#pragma unroll
        for (int ni = 0; ni < 2; ni++) {
            int f = n0w + ni * 8 + 2 * lq;
            g_hs[f * NCOLS + n1]       = __float2half(cs1 * acc[ni][0]);
            g_hs[(f + 1) * NCOLS + n1] = __float2half(cs1 * acc[ni][1]);
            g_hs[f * NCOLS + n2]       = __float2half(cs2 * acc[ni][2]);
            g_hs[(f + 1) * NCOLS + n2] = __float2half(cs2 * acc[ni][3]);
        }
    }
}

// ---------------- kernel 4: fp16 GEMM  out = E[16384x4096] @ Hs^T, cp.async 3-stage ----------------
// CTA: M tile 64, N = 128, K-chunk 32; 256 CTAs, 256 threads
#define GSTG_A (64 * 40)    // halves per A stage
#define GSTG_B (128 * 40)   // halves per B stage
__global__ __launch_bounds__(256, 2) void k_gemm2(float* __restrict__ out) {
    __shared__ __half As[3 * GSTG_A];   // 15 KB
    __shared__ __half Bs[3 * GSTG_B];   // 30 KB
    const int t = threadIdx.x;
    const int warp = t >> 5, lane = t & 31;
    const int lr = lane >> 2, lq = lane & 3;
    const int m0w = (warp >> 2) * 32;       // 2 warps along M
    const int n0w = (warp & 3) * 32;        // 4 warps along N
    const int bm = blockIdx.x;
    const int rl = t >> 2, seg = t & 3;     // A loader: row rl (0..63), cols seg*8
    const int rb = t >> 1, cbh = (t & 1) * 16; // B loader: row rb (0..127), cols cbh, cbh+8

    float acc[2][4][4];
#pragma unroll
    for (int a = 0; a < 2; a++)
#pragma unroll
        for (int b = 0; b < 4; b++)
#pragma unroll
            for (int c = 0; c < 4; c++) acc[a][b][c] = 0.f;

    const unsigned as0 = smem_u32(As), bs0 = smem_u32(Bs);
    const unsigned a_dst = as0 + (rl * 40 + seg * 8) * 2;
    const unsigned b_dst = bs0 + (rb * 40 + cbh) * 2;
    const __half* a_src = g_e + (size_t)(bm * 64 + rl) * NCOLS + seg * 8;
    const __half* b_src = g_hs + rb * NCOLS + cbh;

    auto ISSUE = [&](int it) {
        const int st = it % 3;
        const int col = it * 32;
        CP16(a_dst + st * GSTG_A * 2, a_src + col);
        CP16(b_dst + st * GSTG_B * 2, b_src + col);
        CP16(b_dst + st * GSTG_B * 2 + 16, b_src + col + 8);
    };
    ISSUE(0); CP_COMMIT();
    ISSUE(1); CP_COMMIT();

    const int arow = m0w + (lane & 7) + ((lane >> 3) & 1) * 8;
    const int acol = ((lane >> 4) & 1) * 8;

    for (int it = 0; it < NCOLS / 32; ++it) {
        CP_WAIT1();
        __syncthreads();
        if (it + 2 < NCOLS / 32) ISSUE(it + 2);
        CP_COMMIT();

        const int st = it % 3;
        const unsigned asb = as0 + st * GSTG_A * 2;
        const __half* bsp = Bs + st * GSTG_B;
#pragma unroll
        for (int kk = 0; kk < 32; kk += 16) {
            unsigned a[2][4];
#pragma unroll
            for (int mi = 0; mi < 2; mi++) {
                unsigned addr = asb + ((arow + mi * 16) * 40 + kk + acol) * 2;
                asm volatile("ldmatrix.sync.aligned.m8n8.x4.shared.b16 {%0,%1,%2,%3}, [%4];"
                             : "=r"(a[mi][0]), "=r"(a[mi][1]), "=r"(a[mi][2]), "=r"(a[mi][3])
                             : "r"(addr));
            }
#pragma unroll
            for (int ni = 0; ni < 4; ni++) {
                const int nrow = n0w + ni * 8 + lr;
                unsigned b0 = *(const unsigned*)&bsp[nrow * 40 + kk + 2 * lq];
                unsigned b1 = *(const unsigned*)&bsp[nrow * 40 + kk + 2 * lq + 8];
                mma_f16(acc[0][ni], a[0], b0, b1);
                mma_f16(acc[1][ni], a[1], b0, b1);
            }
        }
    }

    // epilogue: global row i = c*4096 + n  ->  out[n*512 + c*128 + f]
#pragma unroll
    for (int mi = 0; mi < 2; mi++) {
        int i0 = bm * 64 + m0w + mi * 16 + lr;
        int i2 = i0 + 8;
#pragma unroll
        for (int ni = 0; ni < 4; ni++) {
            int f = n0w + ni * 8 + 2 * lq;
            *(float2*)(out + (i0 & 4095) * 512 + (i0 >> 12) * 128 + f) =
                make_float2(acc[mi][ni][0], acc[mi][ni][1]);
            *(float2*)(out + (i2 & 4095) * 512 + (i2 >> 12) * 128 + f) =
                make_float2(acc[mi][ni][2], acc[mi][ni][3]);
        }
    }
}

// ---------------- launch ----------------
extern "C" void kernel_launch(void* const* d_in, const int* in_sizes, int n_in,
                              void* d_out, int out_size) {
    const float* x   = (const float*)d_in[0];
    const float* att = (const float*)d_in[1];
    const float* W   = (const float*)d_in[2];
    const unsigned char* mask = (const unsigned char*)d_in[3];
    float* out = (float*)d_out;

    k_initdet<<<17, 256>>>(mask);
    k_stats1<<<NROWS / 64, 1024>>>(att);
    k_stats2e<<<NROWS / 64, 1024>>>(att, mask);
    k_h<<<NCOLS / 16, 256>>>(x, W);
    k_gemm2<<<NROWS / 64, 256>>>(out);
}